// round 3
// baseline (speedup 1.0000x reference)
#include <cuda_runtime.h>

// Problem constants
#define Bc 64
#define Kc 5
#define Hc 320
#define Wc 320
#define Nc (Hc * Wc)        // 102400 pixels per (b,k)
#define NGc (Nc / 4)        // 25600 float4 groups
#define BPB 9               // blocks per batch -> 576 total = one resident wave @ 4 CTA/SM
#define THREADS 256
#define TOTAL_BLOCKS (Bc * BPB)

// Per-block partial sums: [b][block][32] (cols 0..25 used). Overwritten every launch.
__device__ float g_scratch[Bc * BPB * 32];
// Last-block-done counter. atomicInc with limit TOTAL_BLOCKS-1 wraps back to 0
// after exactly TOTAL_BLOCKS increments -> self-resetting across graph replays.
__device__ unsigned int g_cnt = 0;

// Per-element update. 3 MUFU ops (EX2, RCP, LG2) per element = ~23us chip-wide
// on the otherwise-idle MUFU pipe, matching the ~23us HBM floor; fma pipe stays
// well below both.
__device__ __forceinline__ void elem(float x, float fg,
                                     float& S, float& I, float& C,
                                     float& XS, float& XF)
{
    const float t  = fabsf(x);
    const float e  = __expf(-t);                 // FMUL + MUFU.EX2
    const float u  = 1.0f + e;
    const float rc = __fdividef(1.0f, u);        // MUFU.RCP
    const float p  = (x >= 0.0f) ? rc : (1.0f - rc);   // sigmoid(x)
    const float sp = __logf(u);                  // log1p(e) = MUFU.LG2 + FMUL

    C += fmaxf(x, 0.0f) + sp;                    // alignment-independent BCE part
    S += p;
    I  = fmaf(p, fg, I);
    XS += x;
    XF = fmaf(x, fg, XF);
}

__global__ __launch_bounds__(THREADS, 4)
void hung_fused(const float* __restrict__ slot, const float* __restrict__ tgt,
                float* __restrict__ out)
{
    const int b = blockIdx.y;
    const int tid = threadIdx.x;

    float acc[26];
#pragma unroll
    for (int i = 0; i < 26; i++) acc[i] = 0.0f;

    const float4* tg4 = reinterpret_cast<const float4*>(tgt) + (size_t)b * NGc;
    const float4* sl4 = reinterpret_cast<const float4*>(slot) + (size_t)b * Kc * NGc;

    for (int g = blockIdx.x * THREADS + tid; g < NGc; g += BPB * THREADS) {
        const float4 fg = __ldg(&tg4[g]);
        acc[25] += (fg.x + fg.y) + (fg.z + fg.w);
#pragma unroll
        for (int k = 0; k < Kc; k++) {
            const float4 xv = __ldg(&sl4[(size_t)k * NGc + g]);
            elem(xv.x, fg.x, acc[k*5+0], acc[k*5+1], acc[k*5+2], acc[k*5+3], acc[k*5+4]);
            elem(xv.y, fg.y, acc[k*5+0], acc[k*5+1], acc[k*5+2], acc[k*5+3], acc[k*5+4]);
            elem(xv.z, fg.z, acc[k*5+0], acc[k*5+1], acc[k*5+2], acc[k*5+3], acc[k*5+4]);
            elem(xv.w, fg.w, acc[k*5+0], acc[k*5+1], acc[k*5+2], acc[k*5+3], acc[k*5+4]);
        }
    }

    // Block reduction: warp shuffle then cross-warp via shared (deterministic).
#pragma unroll
    for (int i = 0; i < 26; i++) {
        float v = acc[i];
#pragma unroll
        for (int o = 16; o > 0; o >>= 1) v += __shfl_xor_sync(0xffffffffu, v, o);
        acc[i] = v;
    }
    __shared__ float sm[THREADS / 32][26];
    __shared__ float colsum[26];
    const int warp = tid >> 5, lane = tid & 31;
    if (lane == 0) {
#pragma unroll
        for (int i = 0; i < 26; i++) sm[warp][i] = acc[i];
    }
    __syncthreads();
    if (tid < 26) {
        float s = 0.0f;
#pragma unroll
        for (int w = 0; w < THREADS / 32; w++) s += sm[w][tid];
        colsum[tid] = s;
    }
    __syncthreads();

    // Thread 0 publishes this block's partials and increments the done-counter.
    // Stores + release fence + atomic all from the same thread => formally ordered.
    __shared__ unsigned int s_last;
    if (tid == 0) {
        float* dst = &g_scratch[((size_t)b * BPB + blockIdx.x) * 32];
#pragma unroll
        for (int i = 0; i < 26; i++) dst[i] = colsum[i];
        __threadfence();
        s_last = (atomicInc(&g_cnt, TOTAL_BLOCKS - 1) == TOTAL_BLOCKS - 1) ? 1u : 0u;
    }
    __syncthreads();
    if (s_last == 0u) return;

    // ---- Winner block: finalize (reads ~60KB from L2 with high MLP) ----
    __shared__ float sa[Bc][32];
    __shared__ float red[Bc];
    for (int s = tid; s < Bc * 32; s += THREADS) {
        const int bb = s >> 5, i = s & 31;
        float v = 0.0f;
        if (i < 26) {
#pragma unroll
            for (int j = 0; j < BPB; j++)
                v += __ldcg(&g_scratch[((size_t)bb * BPB + j) * 32 + i]);
        }
        sa[bb][i] = v;
    }
    __syncthreads();

    if (tid < Bc) {
        const float* a = sa[tid];
        const float Tfg = a[25];
        const float Tbg = (float)Nc - Tfg;
        float sumC = 0.0f, sumXS = 0.0f, sumXF = 0.0f;
        float best = 3.4e38f, selXS = 0.0f, selXF = 0.0f;
#pragma unroll
        for (int k = 0; k < Kc; k++) {
            const float S  = a[k*5+0];
            const float I  = a[k*5+1];
            const float Cv = a[k*5+2];
            const float XS = a[k*5+3];
            const float XF = a[k*5+4];
            const float Ib = S - I;
            const float cfg = 1.0f - I  / (S + Tfg - I  + 1e-6f);
            const float cbg = 1.0f - Ib / (S + Tbg - Ib + 1e-6f);
            const float score = cfg - cbg;   // perm cost differs only by this term
            if (score < best) { best = score; selXS = XS; selXF = XF; }  // ties -> smallest k
            sumC += Cv; sumXS += XS; sumXF += XF;
        }
        // loss_b = sum_k C_k - [XF_k0 + sum_{k!=k0}(XS_k - XF_k)]
        red[tid] = sumC - sumXS + sumXF + selXS - 2.0f * selXF;
    }
    __syncthreads();
    if (tid == 0) {
        float tot = 0.0f;
#pragma unroll
        for (int i = 0; i < Bc; i++) tot += red[i];
        out[0] = tot * (1.0f / ((float)Bc * (float)Kc * (float)Nc));
    }
}

extern "C" void kernel_launch(void* const* d_in, const int* in_sizes, int n_in,
                              void* d_out, int out_size)
{
    // metadata order: fg_logits (unused by reference), slot_logits, target
    const float* slot = (const float*)d_in[1];
    const float* tgt  = (const float*)d_in[2];
    float* out = (float*)d_out;

    dim3 grid(BPB, Bc);
    hung_fused<<<grid, THREADS>>>(slot, tgt, out);
}